// round 8
// baseline (speedup 1.0000x reference)
#include <cuda_runtime.h>

// out[t][l][d]: l==0 -> inputs[t][d], else memory[l][d]
// T=2048, L=64, D=1024 fp32. Pure store-bandwidth kernel (512 MiB writes,
// ~91% of HBM spec achieved). Exact R2 winning shape (grid 16384, U=8,
// float4, batched loads then stores), A/B: default write-back stores instead
// of .cs — lets the 126 MB L2 aggregate and schedule HBM writebacks in
// row-hit bursts. Tail reuse set is only 258 KiB, so write-allocate
// pollution is irrelevant.

static constexpr int T = 2048;
static constexpr int L = 64;
static constexpr int D4 = 1024 / 4;            // 256 float4 per row
static constexpr int ROWS = T * L;             // 131072
static constexpr int U = 8;                    // rows per block

__global__ __launch_bounds__(256, 8)
void sliding_window_memory_kernel(const float4* __restrict__ in,
                                  const float4* __restrict__ mem,
                                  float4* __restrict__ out)
{
    const int tid = threadIdx.x;
    const int row0 = blockIdx.x * U;

    float4* __restrict__ o = out + (long)row0 * D4 + tid;

    float4 v[U];
#pragma unroll
    for (int u = 0; u < U; ++u) {
        const int row = row0 + u;
        const int l = row & (L - 1);
        const int t = row >> 6;
        const float4* __restrict__ s =
            (l == 0) ? (in + t * D4 + tid) : (mem + l * D4 + tid);
        v[u] = __ldg(s);                  // in: DRAM once; mem tail: L2-resident
    }
#pragma unroll
    for (int u = 0; u < U; ++u) {
        o[u * D4] = v[u];                 // default write-back store
    }
}

extern "C" void kernel_launch(void* const* d_in, const int* in_sizes, int n_in,
                              void* d_out, int out_size)
{
    const float4* in  = (const float4*)d_in[0];   // inputs [T, D] fp32
    const float4* mem = (const float4*)d_in[1];   // memory [L, D] fp32
    float4* out = (float4*)d_out;                 // [T, L, D] fp32

    const int threads = 256;
    const int blocks = ROWS / U;                  // 16384
    sliding_window_memory_kernel<<<blocks, threads>>>(in, mem, out);
}

// round 9
// speedup vs baseline: 1.1143x; 1.1143x over previous
#include <cuda_runtime.h>

// out[t][l][d]: l==0 -> inputs[t][d], else memory[l][d]
// T=2048, L=64, D=1024 fp32. Pure store-bandwidth kernel (512 MiB writes,
// ~91% of HBM spec achieved; .cs streaming stores confirmed best in R8 A/B).
//
// R2 body with U=4 instead of 8: halves the front-batched LDG count
// (oe*MLP_p1: 64 -> 32) to cut cross-CTA L1tex-queue completion spread,
// while keeping index-math amortization (~4% alu).

static constexpr int T = 2048;
static constexpr int L = 64;
static constexpr int D4 = 1024 / 4;            // 256 float4 per row
static constexpr int ROWS = T * L;             // 131072
static constexpr int U = 4;                    // rows per block

__global__ __launch_bounds__(256, 8)
void sliding_window_memory_kernel(const float4* __restrict__ in,
                                  const float4* __restrict__ mem,
                                  float4* __restrict__ out)
{
    const int tid = threadIdx.x;
    const int row0 = blockIdx.x * U;

    float4* __restrict__ o = out + (long)row0 * D4 + tid;

    float4 v[U];
#pragma unroll
    for (int u = 0; u < U; ++u) {
        const int row = row0 + u;
        const int l = row & (L - 1);
        const int t = row >> 6;
        const float4* __restrict__ s =
            (l == 0) ? (in + t * D4 + tid) : (mem + l * D4 + tid);
        v[u] = __ldg(s);                  // in: DRAM once; mem tail: L2-resident
    }
#pragma unroll
    for (int u = 0; u < U; ++u) {
        __stcs(o + u * D4, v[u]);         // streaming store (R8: beats write-back)
    }
}

extern "C" void kernel_launch(void* const* d_in, const int* in_sizes, int n_in,
                              void* d_out, int out_size)
{
    const float4* in  = (const float4*)d_in[0];   // inputs [T, D] fp32
    const float4* mem = (const float4*)d_in[1];   // memory [L, D] fp32
    float4* out = (float4*)d_out;                 // [T, L, D] fp32

    const int threads = 256;
    const int blocks = ROWS / U;                  // 32768
    sliding_window_memory_kernel<<<blocks, threads>>>(in, mem, out);
}

// round 10
// speedup vs baseline: 1.1196x; 1.0048x over previous
#include <cuda_runtime.h>

// out[t][l][d]: l==0 -> inputs[t][d], else memory[l][d]
// T=2048, L=64, D=1024 fp32. Pure store-bandwidth kernel (512 MiB writes).
//
// Spread-model tuning: U=2 rows/block puts oe*MLP_p1 = 8*2 = 16 right at the
// B300 cross-CTA L1tex-queue contention knee (U=8: 64 -> 75.0us; U=4: 32 ->
// 74.2us). ALU/issue have headroom (3.8%/9.4%), so the extra index math per
// byte is free. .cs streaming stores (R8 A/B: beats write-back by 8us).

static constexpr int T = 2048;
static constexpr int L = 64;
static constexpr int D4 = 1024 / 4;            // 256 float4 per row
static constexpr int ROWS = T * L;             // 131072
static constexpr int U = 2;                    // rows per block

__global__ __launch_bounds__(256, 8)
void sliding_window_memory_kernel(const float4* __restrict__ in,
                                  const float4* __restrict__ mem,
                                  float4* __restrict__ out)
{
    const int tid = threadIdx.x;
    const int row0 = blockIdx.x * U;

    float4* __restrict__ o = out + (long)row0 * D4 + tid;

    float4 v[U];
#pragma unroll
    for (int u = 0; u < U; ++u) {
        const int row = row0 + u;
        const int l = row & (L - 1);
        const int t = row >> 6;
        const float4* __restrict__ s =
            (l == 0) ? (in + t * D4 + tid) : (mem + l * D4 + tid);
        v[u] = __ldg(s);                  // in: DRAM once; mem tail: L2-resident
    }
#pragma unroll
    for (int u = 0; u < U; ++u) {
        __stcs(o + u * D4, v[u]);         // streaming store
    }
}

extern "C" void kernel_launch(void* const* d_in, const int* in_sizes, int n_in,
                              void* d_out, int out_size)
{
    const float4* in  = (const float4*)d_in[0];   // inputs [T, D] fp32
    const float4* mem = (const float4*)d_in[1];   // memory [L, D] fp32
    float4* out = (float4*)d_out;                 // [T, L, D] fp32

    const int threads = 256;
    const int blocks = ROWS / U;                  // 65536
    sliding_window_memory_kernel<<<blocks, threads>>>(in, mem, out);
}